// round 3
// baseline (speedup 1.0000x reference)
#include <cuda_runtime.h>

// ---------------------------------------------------------------------------
// RealVirtualAttention:
//   1) masked segment-mean over sorted batch (real vs virtual nodes) -> [B,2,D]
//   2) HAN semantic attention: score_m = sum_b q^T tanh(W1^T x_{b,m} + b1)
//      beta = softmax(score / B)
//   3) out[b] = beta0 * mean_real[b] + beta1 * mean_virtual[b]
// ---------------------------------------------------------------------------

#define VIRTUAL_Z 100
#define MAXB 8192
#define MAXD 256
#define SGPB 16                    // graphs per block in score kernel
#define SVPB (2*SGPB)              // vectors per block
#define NVW  8                     // vectors per warp (SVPB / 4 warps)

__device__ float g_means[(size_t)MAXB * 2 * MAXD];   // [B][2][D] means
__device__ float g_part[(MAXB / SGPB) * 2 + 2];      // per-block partial scores
__device__ float g_score[2];
__device__ int   g_is64;
__device__ int   g_bounds[MAXB + 1];                 // row range per graph
__device__ unsigned int g_count;                     // score-block completion ctr

// ---------------------------------------------------------------------------
// Bounds kernel: g_bounds[b] = first row index with batch >= b.
// Also detects int32 vs int64 (jax silently downcasts int64 -> int32 when x64
// is disabled): viewing as int32, odd slots near the end are 0 iff int64.
// Also resets g_count for the score kernel's last-block election.
// ---------------------------------------------------------------------------
__global__ void bounds_kernel(const int* __restrict__ bat32, int N, int B) {
    __shared__ int s_is64;
    if (threadIdx.x == 0) {
        int is64 = 1;
        int idx = N - 1;
        if ((idx & 1) == 0) idx--;
        for (int k = 0; k < 8 && idx >= 1; k++, idx -= 2) {
            if (bat32[idx] != 0) { is64 = 0; break; }
        }
        s_is64 = is64;
        if (blockIdx.x == 0) { g_is64 = is64; g_count = 0u; }
    }
    __syncthreads();
    const int s = s_is64;
    const int i = blockIdx.x * blockDim.x + threadIdx.x;
    if (i >= N) return;
    const int cur  = bat32[(size_t)i << s];
    const int prev = (i == 0) ? -1 : bat32[(size_t)(i - 1) << s];
    for (int b = prev + 1; b <= cur; b++) g_bounds[b] = i;
    if (i == N - 1) {
        for (int b = cur + 1; b <= B; b++) g_bounds[b] = N;
    }
}

// ---------------------------------------------------------------------------
// Kernel 1 (hot): one block per graph, thread t owns feature pair (2t, 2t+1).
// 8-row software pipeline: batch all loads (8 z broadcasts + 8 float2) before
// accumulation -> MLP >= 8 per thread, float2 halves LDG count.
// Row stride D*4 bytes is 8-aligned for even D -> float2 is always legal.
// ---------------------------------------------------------------------------
__global__ void seg_mean_vec_kernel(const float* __restrict__ x,
                                    const int*   __restrict__ z32,
                                    int D) {
    const int b = blockIdx.x;
    const int s = g_is64;
    const int start = g_bounds[b];
    const int end   = g_bounds[b + 1];
    const int t  = threadIdx.x;
    const int D2 = D >> 1;
    const float2* __restrict__ x2 = reinterpret_cast<const float2*>(x);

    float2 sr = make_float2(0.f, 0.f);
    float2 sv = make_float2(0.f, 0.f);
    int cr = 0, cv = 0;

    int i = start;
    for (; i + 8 <= end; i += 8) {
        int zz[8];
        float2 v[8];
        #pragma unroll
        for (int k = 0; k < 8; k++) zz[k] = z32[(size_t)(i + k) << s];
        #pragma unroll
        for (int k = 0; k < 8; k++) {
            v[k] = (t < D2) ? __ldcs(&x2[(size_t)(i + k) * D2 + t])
                            : make_float2(0.f, 0.f);
        }
        #pragma unroll
        for (int k = 0; k < 8; k++) {
            if (zz[k] != VIRTUAL_Z) { sr.x += v[k].x; sr.y += v[k].y; cr++; }
            else                    { sv.x += v[k].x; sv.y += v[k].y; cv++; }
        }
    }
    for (; i < end; i++) {
        const int zz = z32[(size_t)i << s];
        float2 v = (t < D2) ? __ldcs(&x2[(size_t)i * D2 + t])
                            : make_float2(0.f, 0.f);
        if (zz != VIRTUAL_Z) { sr.x += v.x; sr.y += v.y; cr++; }
        else                 { sv.x += v.x; sv.y += v.y; cv++; }
    }

    if (t < D2) {
        const float ir = 1.f / (float)max(cr, 1);
        const float iv = 1.f / (float)max(cv, 1);
        float* mr = g_means + (size_t)b * 2 * D;
        reinterpret_cast<float2*>(mr)[t]     = make_float2(sr.x * ir, sr.y * ir);
        reinterpret_cast<float2*>(mr + D)[t] = make_float2(sv.x * iv, sv.y * iv);
    }
}

// Scalar fallback for odd D (not hit for this problem's shapes).
__global__ void seg_mean_scalar_kernel(const float* __restrict__ x,
                                       const int*   __restrict__ z32,
                                       int D) {
    const int b = blockIdx.x;
    const int s = g_is64;
    const int start = g_bounds[b];
    const int end   = g_bounds[b + 1];
    const int t = threadIdx.x;

    float sr = 0.f, sv = 0.f;
    int cr = 0, cv = 0;
    for (int i = start; i < end; i++) {
        const int zz = z32[(size_t)i << s];
        float v = (t < D) ? x[(size_t)i * D + t] : 0.f;
        if (zz != VIRTUAL_Z) { sr += v; cr++; } else { sv += v; cv++; }
    }
    if (t < D) {
        float* mr = g_means + (size_t)b * 2 * D;
        mr[t]     = sr / (float)max(cr, 1);
        mr[D + t] = sv / (float)max(cv, 1);
    }
}

// ---------------------------------------------------------------------------
// Kernel 2: semantic attention scores, register-blocked.
// Block = 128 threads (4 warps), SGPB=16 graphs (SVPB=32 vectors).
// Lane owns 4 consecutive aa columns (one warp spans 128 aa via float4 W1
// loads); each warp handles NVW=8 vectors -> 32 fp32 accumulators.
// Per 4-d chunk per warp: 8 LDS.128 + 4 LDG.128 + 128 FMA (91% FMA mix).
// Last block (atomic-counter elect) does the fixed-order final reduction.
// Requires A % 4 == 0.
// ---------------------------------------------------------------------------
__global__ void score_kernel(const float* __restrict__ W1,
                             const float* __restrict__ b1,
                             const float* __restrict__ q,
                             int D, int Dp, int A, int B, int nblk) {
    extern __shared__ float sx[];   // [SVPB][Dp]
    __shared__ float r0[4], r1[4];
    __shared__ int   s_last;

    const int b0 = blockIdx.x * SGPB;
    const int nv = min(SVPB, 2 * (B - b0));   // valid vectors in this block

    // Stage x vectors into shared memory (zero padding).
    for (int i = threadIdx.x; i < SVPB * Dp; i += blockDim.x) {
        const int v = i / Dp;
        const int d = i - v * Dp;
        float val = 0.f;
        if (v < nv && d < D) val = g_means[((size_t)b0 * 2 + v) * D + d];
        sx[i] = val;
    }
    __syncthreads();

    const int warp  = threadIdx.x >> 5;
    const int lane  = threadIdx.x & 31;
    const int vbase = warp * NVW;
    float t0 = 0.f, t1 = 0.f;

    for (int abase = 0; abase < A; abase += 128) {
        const int  aa = abase + lane * 4;
        const bool av = (aa < A);             // A % 4 == 0 -> full float4 valid

        float acc[NVW][4];
        #pragma unroll
        for (int v = 0; v < NVW; v++)
            #pragma unroll
            for (int c = 0; c < 4; c++) acc[v][c] = 0.f;

        for (int d = 0; d < Dp; d += 4) {
            float4 w[4];
            #pragma unroll
            for (int j = 0; j < 4; j++) {
                w[j] = (av && (d + j) < D)
                     ? *reinterpret_cast<const float4*>(&W1[(size_t)(d + j) * A + aa])
                     : make_float4(0.f, 0.f, 0.f, 0.f);
            }
            #pragma unroll
            for (int v = 0; v < NVW; v++) {
                const float4 xv =
                    *reinterpret_cast<const float4*>(&sx[(vbase + v) * Dp + d]);
                acc[v][0] = fmaf(xv.x, w[0].x, acc[v][0]);
                acc[v][1] = fmaf(xv.x, w[0].y, acc[v][1]);
                acc[v][2] = fmaf(xv.x, w[0].z, acc[v][2]);
                acc[v][3] = fmaf(xv.x, w[0].w, acc[v][3]);
                acc[v][0] = fmaf(xv.y, w[1].x, acc[v][0]);
                acc[v][1] = fmaf(xv.y, w[1].y, acc[v][1]);
                acc[v][2] = fmaf(xv.y, w[1].z, acc[v][2]);
                acc[v][3] = fmaf(xv.y, w[1].w, acc[v][3]);
                acc[v][0] = fmaf(xv.z, w[2].x, acc[v][0]);
                acc[v][1] = fmaf(xv.z, w[2].y, acc[v][1]);
                acc[v][2] = fmaf(xv.z, w[2].z, acc[v][2]);
                acc[v][3] = fmaf(xv.z, w[2].w, acc[v][3]);
                acc[v][0] = fmaf(xv.w, w[3].x, acc[v][0]);
                acc[v][1] = fmaf(xv.w, w[3].y, acc[v][1]);
                acc[v][2] = fmaf(xv.w, w[3].z, acc[v][2]);
                acc[v][3] = fmaf(xv.w, w[3].w, acc[v][3]);
            }
        }

        // Epilogue: bias + tanh + q, accumulate per metapath.
        float4 b4 = make_float4(0.f, 0.f, 0.f, 0.f);
        float4 q4 = make_float4(0.f, 0.f, 0.f, 0.f);
        if (av) {
            b4 = *reinterpret_cast<const float4*>(&b1[aa]);
            q4 = *reinterpret_cast<const float4*>(&q[aa]);
        }
        #pragma unroll
        for (int v = 0; v < NVW; v++) {
            const int vv = vbase + v;
            float tv = 0.f;
            if (av && vv < nv) {
                tv = tanhf(acc[v][0] + b4.x) * q4.x
                   + tanhf(acc[v][1] + b4.y) * q4.y
                   + tanhf(acc[v][2] + b4.z) * q4.z
                   + tanhf(acc[v][3] + b4.w) * q4.w;
            }
            if (vv & 1) t1 += tv; else t0 += tv;
        }
    }

    // Warp reduce (fixed shuffle pattern -> deterministic)
    #pragma unroll
    for (int off = 16; off; off >>= 1) {
        t0 += __shfl_down_sync(0xffffffffu, t0, off);
        t1 += __shfl_down_sync(0xffffffffu, t1, off);
    }
    if (lane == 0) { r0[warp] = t0; r1[warp] = t1; }
    if (threadIdx.x == 0) s_last = 0;
    __syncthreads();

    if (threadIdx.x == 0) {
        float s0 = r0[0] + r0[1] + r0[2] + r0[3];
        float s1 = r1[0] + r1[1] + r1[2] + r1[3];
        g_part[2 * blockIdx.x + 0] = s0;
        g_part[2 * blockIdx.x + 1] = s1;
        __threadfence();
        const unsigned int done = atomicAdd(&g_count, 1u);
        if (done == (unsigned int)(nblk - 1)) s_last = 1;
    }
    __syncthreads();

    // Last block: fixed-order final reduction over all partials.
    if (s_last && warp == 0) {
        float a0 = 0.f, a1 = 0.f;
        for (int i = lane; i < nblk; i += 32) {
            a0 += g_part[2 * i + 0];
            a1 += g_part[2 * i + 1];
        }
        #pragma unroll
        for (int off = 16; off; off >>= 1) {
            a0 += __shfl_down_sync(0xffffffffu, a0, off);
            a1 += __shfl_down_sync(0xffffffffu, a1, off);
        }
        if (lane == 0) { g_score[0] = a0; g_score[1] = a1; }
    }
}

// ---------------------------------------------------------------------------
// Kernel 3: beta = softmax(score / B); out[b,d] = beta0*mean_r + beta1*mean_v
// ---------------------------------------------------------------------------
__global__ void combine_kernel(float* __restrict__ outp, int B, int D) {
    const float invB = 1.f / (float)B;
    const float s0 = g_score[0] * invB;
    const float s1 = g_score[1] * invB;
    const float mx = fmaxf(s0, s1);
    const float e0 = expf(s0 - mx);
    const float e1 = expf(s1 - mx);
    const float beta0 = e0 / (e0 + e1);
    const float beta1 = 1.f - beta0;

    const int idx = blockIdx.x * blockDim.x + threadIdx.x;
    const int tot = B * D;
    if (idx < tot) {
        const int b = idx / D;
        const int d = idx - b * D;
        const float* mr = g_means + (size_t)b * 2 * D;
        outp[idx] = mr[d] * beta0 + mr[D + d] * beta1;
    }
}

// ---------------------------------------------------------------------------
extern "C" void kernel_launch(void* const* d_in, const int* in_sizes, int n_in,
                              void* d_out, int out_size) {
    const float* x   = (const float*)d_in[0];   // out [N, D] fp32
    const int*   z   = (const int*)d_in[1];     // z   [N] int32/int64
    const int*   bat = (const int*)d_in[2];     // batch [N] sorted int32/int64
    const float* W1  = (const float*)d_in[3];   // [D, A]
    const float* b1  = (const float*)d_in[4];   // [A]
    const float* q   = (const float*)d_in[5];   // [A, 1]

    const int N = in_sizes[1];
    const int D = in_sizes[0] / N;
    const int A = in_sizes[4];
    const int B = out_size / D;

    bounds_kernel<<<(N + 255) / 256, 256>>>(bat, N, B);

    if ((D & 1) == 0) {
        const int D2 = D >> 1;
        int tpb = ((D2 + 31) / 32) * 32;
        if (tpb > 1024) tpb = 1024;
        seg_mean_vec_kernel<<<B, tpb>>>(x, z, D);
    } else {
        int tpb = ((D + 31) / 32) * 32;
        if (tpb > 1024) tpb = 1024;
        seg_mean_scalar_kernel<<<B, tpb>>>(x, z, D);
    }

    const int Dp = (D + 3) & ~3;
    const int nblk2 = (B + SGPB - 1) / SGPB;
    const size_t shmem = (size_t)SVPB * Dp * sizeof(float);
    score_kernel<<<nblk2, 128, shmem>>>(W1, b1, q, D, Dp, A, B, nblk2);

    const int tot = B * D;
    combine_kernel<<<(tot + 255) / 256, 256>>>((float*)d_out, B, D);
}

// round 4
// speedup vs baseline: 1.0517x; 1.0517x over previous
#include <cuda_runtime.h>

// ---------------------------------------------------------------------------
// RealVirtualAttention:
//   1) masked segment-mean over sorted batch (real vs virtual nodes) -> [B,2,D]
//   2) HAN semantic attention: score_m = sum_b q^T tanh(W1^T x_{b,m} + b1)
//      beta = softmax(score / B)
//   3) out[b] = beta0 * mean_real[b] + beta1 * mean_virtual[b]
// ---------------------------------------------------------------------------

#define VIRTUAL_Z 100
#define MAXB 8192
#define MAXD 256
#define SGPB 4                     // graphs per block in score kernel
#define SVPB (2*SGPB)              // vectors per block (8)

__device__ float g_means[(size_t)MAXB * 2 * MAXD];   // [B][2][D] means
__device__ float g_part[(MAXB / SGPB) * 2 + 2];      // per-block partial scores
__device__ float g_score[2];
__device__ int   g_is64;
__device__ int   g_bounds[MAXB + 1];                 // row range per graph
__device__ unsigned int g_count;                     // score-block completion ctr

// ---------------------------------------------------------------------------
// Bounds kernel: g_bounds[b] = first row index with batch >= b.
// Also detects int32 vs int64 (jax silently downcasts int64 -> int32 when x64
// is disabled): viewing as int32, odd slots near the end are 0 iff int64.
// Also resets g_count for the score kernel's last-block election.
// ---------------------------------------------------------------------------
__global__ void bounds_kernel(const int* __restrict__ bat32, int N, int B) {
    __shared__ int s_is64;
    if (threadIdx.x == 0) {
        int is64 = 1;
        int idx = N - 1;
        if ((idx & 1) == 0) idx--;
        for (int k = 0; k < 8 && idx >= 1; k++, idx -= 2) {
            if (bat32[idx] != 0) { is64 = 0; break; }
        }
        s_is64 = is64;
        if (blockIdx.x == 0) { g_is64 = is64; g_count = 0u; }
    }
    __syncthreads();
    const int s = s_is64;
    const int i = blockIdx.x * blockDim.x + threadIdx.x;
    if (i >= N) return;
    const int cur  = bat32[(size_t)i << s];
    const int prev = (i == 0) ? -1 : bat32[(size_t)(i - 1) << s];
    for (int b = prev + 1; b <= cur; b++) g_bounds[b] = i;
    if (i == N - 1) {
        for (int b = cur + 1; b <= B; b++) g_bounds[b] = N;
    }
}

// ---------------------------------------------------------------------------
// Kernel 1 (hot): one block per graph, thread t owns feature pair (2t, 2t+1).
// 8-row software pipeline: batch all loads (8 z broadcasts + 8 float2) before
// accumulation -> MLP >= 8 per thread, float2 halves LDG count.
// Row stride D*4 bytes is 8-aligned for even D -> float2 is always legal.
// ---------------------------------------------------------------------------
__global__ void seg_mean_vec_kernel(const float* __restrict__ x,
                                    const int*   __restrict__ z32,
                                    int D) {
    const int b = blockIdx.x;
    const int s = g_is64;
    const int start = g_bounds[b];
    const int end   = g_bounds[b + 1];
    const int t  = threadIdx.x;
    const int D2 = D >> 1;
    const float2* __restrict__ x2 = reinterpret_cast<const float2*>(x);

    float2 sr = make_float2(0.f, 0.f);
    float2 sv = make_float2(0.f, 0.f);
    int cr = 0, cv = 0;

    int i = start;
    for (; i + 8 <= end; i += 8) {
        int zz[8];
        float2 v[8];
        #pragma unroll
        for (int k = 0; k < 8; k++) zz[k] = z32[(size_t)(i + k) << s];
        #pragma unroll
        for (int k = 0; k < 8; k++) {
            v[k] = (t < D2) ? __ldcs(&x2[(size_t)(i + k) * D2 + t])
                            : make_float2(0.f, 0.f);
        }
        #pragma unroll
        for (int k = 0; k < 8; k++) {
            if (zz[k] != VIRTUAL_Z) { sr.x += v[k].x; sr.y += v[k].y; cr++; }
            else                    { sv.x += v[k].x; sv.y += v[k].y; cv++; }
        }
    }
    for (; i < end; i++) {
        const int zz = z32[(size_t)i << s];
        float2 v = (t < D2) ? __ldcs(&x2[(size_t)i * D2 + t])
                            : make_float2(0.f, 0.f);
        if (zz != VIRTUAL_Z) { sr.x += v.x; sr.y += v.y; cr++; }
        else                 { sv.x += v.x; sv.y += v.y; cv++; }
    }

    if (t < D2) {
        const float ir = 1.f / (float)max(cr, 1);
        const float iv = 1.f / (float)max(cv, 1);
        float* mr = g_means + (size_t)b * 2 * D;
        reinterpret_cast<float2*>(mr)[t]     = make_float2(sr.x * ir, sr.y * ir);
        reinterpret_cast<float2*>(mr + D)[t] = make_float2(sv.x * iv, sv.y * iv);
    }
}

// Scalar fallback for odd D (not hit for this problem's shapes).
__global__ void seg_mean_scalar_kernel(const float* __restrict__ x,
                                       const int*   __restrict__ z32,
                                       int D) {
    const int b = blockIdx.x;
    const int s = g_is64;
    const int start = g_bounds[b];
    const int end   = g_bounds[b + 1];
    const int t = threadIdx.x;

    float sr = 0.f, sv = 0.f;
    int cr = 0, cv = 0;
    for (int i = start; i < end; i++) {
        const int zz = z32[(size_t)i << s];
        float v = (t < D) ? x[(size_t)i * D + t] : 0.f;
        if (zz != VIRTUAL_Z) { sr += v; cr++; } else { sv += v; cv++; }
    }
    if (t < D) {
        float* mr = g_means + (size_t)b * 2 * D;
        mr[t]     = sr / (float)max(cr, 1);
        mr[D + t] = sv / (float)max(cv, 1);
    }
}

// ---------------------------------------------------------------------------
// Kernel 2: semantic attention scores. Block = 128 threads; each thread owns
// one aa column (striding by 128 if A > 128). SGPB=4 graphs (SVPB=8 vectors)
// per block -> 1024 blocks for B=4096: ~28 warps/SM in flight, enough to hide
// LDS/L1 latency while staying FMA-dominant (12 mem : 32 FMA per 4-d chunk).
// W1 (76.8 KB) stays L1-resident and is shared across blocks on an SM.
// Last block (atomic-counter elect) does the fixed-order final reduction.
// ---------------------------------------------------------------------------
__global__ void score_kernel(const float* __restrict__ W1,
                             const float* __restrict__ b1,
                             const float* __restrict__ q,
                             int D, int Dp, int A, int B, int nblk) {
    extern __shared__ float sx[];   // [SVPB][Dp]
    __shared__ float r0[4], r1[4];
    __shared__ int   s_last;

    const int b0 = blockIdx.x * SGPB;
    const int nv = min(SVPB, 2 * (B - b0));   // valid vectors in this block

    // Stage x vectors into shared memory (zero padding).
    for (int i = threadIdx.x; i < SVPB * Dp; i += blockDim.x) {
        const int v = i / Dp;
        const int d = i - v * Dp;
        float val = 0.f;
        if (v < nv && d < D) val = g_means[((size_t)b0 * 2 + v) * D + d];
        sx[i] = val;
    }
    if (threadIdx.x == 0) s_last = 0;
    __syncthreads();

    const int warp = threadIdx.x >> 5;
    const int lane = threadIdx.x & 31;
    float t0 = 0.f, t1 = 0.f;

    for (int aa = threadIdx.x; aa < A; aa += blockDim.x) {
        float acc[SVPB];
        const float bb = b1[aa];
        #pragma unroll
        for (int v = 0; v < SVPB; v++) acc[v] = bb;

        for (int d = 0; d < Dp; d += 4) {
            const float w0 = (d + 0 < D) ? W1[(size_t)(d + 0) * A + aa] : 0.f;
            const float w1 = (d + 1 < D) ? W1[(size_t)(d + 1) * A + aa] : 0.f;
            const float w2 = (d + 2 < D) ? W1[(size_t)(d + 2) * A + aa] : 0.f;
            const float w3 = (d + 3 < D) ? W1[(size_t)(d + 3) * A + aa] : 0.f;
            #pragma unroll
            for (int v = 0; v < SVPB; v++) {
                const float4 xv = *reinterpret_cast<const float4*>(&sx[v * Dp + d]);
                acc[v] = fmaf(xv.x, w0, acc[v]);
                acc[v] = fmaf(xv.y, w1, acc[v]);
                acc[v] = fmaf(xv.z, w2, acc[v]);
                acc[v] = fmaf(xv.w, w3, acc[v]);
            }
        }

        const float qa = q[aa];
        #pragma unroll
        for (int v = 0; v < SVPB; v++) {
            if (v < nv) {
                const float tv = tanhf(acc[v]) * qa;
                if (v & 1) t1 += tv; else t0 += tv;
            }
        }
    }

    // Warp reduce (fixed shuffle pattern -> deterministic)
    #pragma unroll
    for (int off = 16; off; off >>= 1) {
        t0 += __shfl_down_sync(0xffffffffu, t0, off);
        t1 += __shfl_down_sync(0xffffffffu, t1, off);
    }
    if (lane == 0) { r0[warp] = t0; r1[warp] = t1; }
    __syncthreads();

    if (threadIdx.x == 0) {
        float s0 = r0[0] + r0[1] + r0[2] + r0[3];
        float s1 = r1[0] + r1[1] + r1[2] + r1[3];
        g_part[2 * blockIdx.x + 0] = s0;
        g_part[2 * blockIdx.x + 1] = s1;
        __threadfence();
        const unsigned int done = atomicAdd(&g_count, 1u);
        if (done == (unsigned int)(nblk - 1)) s_last = 1;
    }
    __syncthreads();

    // Last block: fixed-order final reduction over all partials.
    if (s_last && warp == 0) {
        float a0 = 0.f, a1 = 0.f;
        for (int i = lane; i < nblk; i += 32) {
            a0 += g_part[2 * i + 0];
            a1 += g_part[2 * i + 1];
        }
        #pragma unroll
        for (int off = 16; off; off >>= 1) {
            a0 += __shfl_down_sync(0xffffffffu, a0, off);
            a1 += __shfl_down_sync(0xffffffffu, a1, off);
        }
        if (lane == 0) { g_score[0] = a0; g_score[1] = a1; }
    }
}

// ---------------------------------------------------------------------------
// Kernel 3: beta = softmax(score / B); out[b,d] = beta0*mean_r + beta1*mean_v
// float2-vectorized (requires D even; scalar fallback otherwise).
// ---------------------------------------------------------------------------
__global__ void combine_vec_kernel(float2* __restrict__ outp, int B, int D2,
                                   int D) {
    const float invB = 1.f / (float)B;
    const float s0 = g_score[0] * invB;
    const float s1 = g_score[1] * invB;
    const float mx = fmaxf(s0, s1);
    const float e0 = expf(s0 - mx);
    const float e1 = expf(s1 - mx);
    const float beta0 = e0 / (e0 + e1);
    const float beta1 = 1.f - beta0;

    const int idx = blockIdx.x * blockDim.x + threadIdx.x;
    const int tot = B * D2;
    if (idx < tot) {
        const int b = idx / D2;
        const int d = idx - b * D2;
        const float* mrow = g_means + (size_t)b * 2 * D;
        const float2 r = reinterpret_cast<const float2*>(mrow)[d];
        const float2 v = reinterpret_cast<const float2*>(mrow + D)[d];
        outp[idx] = make_float2(r.x * beta0 + v.x * beta1,
                                r.y * beta0 + v.y * beta1);
    }
}

__global__ void combine_scalar_kernel(float* __restrict__ outp, int B, int D) {
    const float invB = 1.f / (float)B;
    const float s0 = g_score[0] * invB;
    const float s1 = g_score[1] * invB;
    const float mx = fmaxf(s0, s1);
    const float e0 = expf(s0 - mx);
    const float e1 = expf(s1 - mx);
    const float beta0 = e0 / (e0 + e1);
    const float beta1 = 1.f - beta0;

    const int idx = blockIdx.x * blockDim.x + threadIdx.x;
    const int tot = B * D;
    if (idx < tot) {
        const int b = idx / D;
        const int d = idx - b * D;
        const float* mr = g_means + (size_t)b * 2 * D;
        outp[idx] = mr[d] * beta0 + mr[D + d] * beta1;
    }
}

// ---------------------------------------------------------------------------
extern "C" void kernel_launch(void* const* d_in, const int* in_sizes, int n_in,
                              void* d_out, int out_size) {
    const float* x   = (const float*)d_in[0];   // out [N, D] fp32
    const int*   z   = (const int*)d_in[1];     // z   [N] int32/int64
    const int*   bat = (const int*)d_in[2];     // batch [N] sorted int32/int64
    const float* W1  = (const float*)d_in[3];   // [D, A]
    const float* b1  = (const float*)d_in[4];   // [A]
    const float* q   = (const float*)d_in[5];   // [A, 1]

    const int N = in_sizes[1];
    const int D = in_sizes[0] / N;
    const int A = in_sizes[4];
    const int B = out_size / D;

    bounds_kernel<<<(N + 255) / 256, 256>>>(bat, N, B);

    if ((D & 1) == 0) {
        const int D2 = D >> 1;
        int tpb = ((D2 + 31) / 32) * 32;
        if (tpb > 1024) tpb = 1024;
        seg_mean_vec_kernel<<<B, tpb>>>(x, z, D);
    } else {
        int tpb = ((D + 31) / 32) * 32;
        if (tpb > 1024) tpb = 1024;
        seg_mean_scalar_kernel<<<B, tpb>>>(x, z, D);
    }

    const int Dp = (D + 3) & ~3;
    const int nblk2 = (B + SGPB - 1) / SGPB;
    const size_t shmem = (size_t)SVPB * Dp * sizeof(float);
    score_kernel<<<nblk2, 128, shmem>>>(W1, b1, q, D, Dp, A, B, nblk2);

    if ((D & 1) == 0) {
        const int D2 = D >> 1;
        const int tot = B * D2;
        combine_vec_kernel<<<(tot + 255) / 256, 256>>>((float2*)d_out, B, D2, D);
    } else {
        const int tot = B * D;
        combine_scalar_kernel<<<(tot + 255) / 256, 256>>>((float*)d_out, B, D);
    }
}